// round 2
// baseline (speedup 1.0000x reference)
#include <cuda_runtime.h>

#define BATCH 4
#define NPTS  4096
#define KNB   16
#define DPD   128
#define DMD   256
#define ROWS  (BATCH * NPTS)   // 16384

// ---------------- scratch (static device globals; no allocations) ----------------
__device__ float  g_Wc[DPD * 768];          // fc1_w @ [wq|wk|wv]  [128,768]
__device__ float  g_bc[768];                // fc1_b @ [wq|wk|wv]
__device__ float  g_fd2T[DMD * DMD];        // fd2^T
__device__ float4 g_pts[ROWS];              // (x,y,z, |xyz|^2)
__device__ int    g_knn[ROWS * KNB];
__device__ float  g_QKV[(size_t)ROWS * 768];// [16384, 768] (q|k|v)
__device__ float  g_QP[ROWS * DMD];         // fd2 @ q per point
__device__ float  g_AV[ROWS * DMD];         // sum_k attn * v
__device__ float  g_HBAR[ROWS * DMD];       // sum_k attn * h
__device__ float  g_RES[ROWS * DMD];

// ---------------- prep: combined qkv weights ----------------
__global__ __launch_bounds__(256) void prep_wc_k(
    const float* __restrict__ fc1w, const float* __restrict__ fc1b,
    const float* __restrict__ wq,   const float* __restrict__ wk,
    const float* __restrict__ wv)
{
    int t = blockIdx.x * 256 + threadIdx.x;   // 0 .. 128*768-1
    int r = t / 768, c = t % 768;
    const float* w = (c < 256) ? wq : (c < 512) ? wk : wv;
    int cc = c & 255;
    float s = 0.f;
#pragma unroll 4
    for (int m = 0; m < 256; m++)
        s = fmaf(__ldg(fc1w + r * 256 + m), __ldg(w + m * 256 + cc), s);
    g_Wc[r * 768 + c] = s;
    if (r == 0) {
        float b = 0.f;
#pragma unroll 4
        for (int m = 0; m < 256; m++)
            b = fmaf(__ldg(fc1b + m), __ldg(w + m * 256 + cc), b);
        g_bc[c] = b;
    }
}

__global__ void transpose_fd2_k(const float* __restrict__ fd2w)
{
    int t = blockIdx.x * 256 + threadIdx.x;   // 65536
    int j = t >> 8, d = t & 255;
    g_fd2T[d * 256 + j] = fd2w[j * 256 + d];
}

__global__ void pack_xyz_k(const float* __restrict__ xyz)
{
    int p = blockIdx.x * 256 + threadIdx.x;   // 16384
    float x = xyz[p * 3], y = xyz[p * 3 + 1], z = xyz[p * 3 + 2];
    float sq = x * x; sq = fmaf(y, y, sq); sq = fmaf(z, z, sq);
    g_pts[p] = make_float4(x, y, z, sq);
}

// ---------------- KNN: brute force, per-thread query, register top-16 ----------------
__global__ __launch_bounds__(64) void knn_kernel()
{
    int p = blockIdx.x * 64 + threadIdx.x;     // 16384
    int b = p >> 12;
    const float4* bp = g_pts + (b << 12);
    float4 me = bp[p & 4095];
    float qx = me.x, qy = me.y, qz = me.z, qsq = me.w;

    float bd[16]; int bi[16];
#pragma unroll
    for (int i = 0; i < 16; i++) { bd[i] = 3.0e38f; bi[i] = 0; }
    float worst = 3.0e38f;

#pragma unroll 4
    for (int j = 0; j < 4096; j++) {
        float4 o = __ldg(bp + j);
        float tt = qx * o.x; tt = fmaf(qy, o.y, tt); tt = fmaf(qz, o.z, tt);
        // exact reference formula: sq_i + sq_j - 2*dot (self -> exactly 0)
        float d2 = fmaf(-2.f, tt, qsq + o.w);
        if (d2 < worst) {
            // fully predicated sorted insert (ascending), all registers
#pragma unroll
            for (int t = 15; t >= 1; t--) {
                bool cm = d2 < bd[t - 1];
                bool ct = d2 < bd[t];
                bd[t] = cm ? bd[t - 1] : (ct ? d2 : bd[t]);
                bi[t] = cm ? bi[t - 1] : (ct ? j  : bi[t]);
            }
            if (d2 < bd[0]) { bd[0] = d2; bi[0] = j; }
            worst = bd[15];
        }
    }
#pragma unroll
    for (int i = 0; i < 16; i++) g_knn[p * 16 + i] = bi[i];
}

// ---------------- SGEMM: 128x128 block tile, 8x8 microtile, BK=8 ----------------
// MODE 0: QKV = features @ g_Wc + g_bc
// MODE 1: QP  = Q(g_QKV cols 0:256, lda=768) @ g_fd2T
// MODE 2: RES = g_HBAR @ fd2_w + fd2_b + g_AV
// MODE 3: OUT = g_RES @ fc2_w + fc2_b + features   (stored transposed [B,DP,N])
template<int MODE>
__global__ __launch_bounds__(256) void sgemm_k(
    const float* __restrict__ Aext, const float* __restrict__ Bext,
    const float* __restrict__ biasExt, const float* __restrict__ addExt,
    float* __restrict__ Cext, int M, int N, int Kd, int lda)
{
    const float* A = (MODE == 0) ? Aext : (MODE == 1) ? g_QKV : (MODE == 2) ? g_HBAR : g_RES;
    const float* B = (MODE == 0) ? g_Wc : (MODE == 1) ? g_fd2T : Bext;
    const float* bias = (MODE == 0) ? g_bc : (MODE == 1) ? (const float*)nullptr : biasExt;
    const float* add  = (MODE == 2) ? g_AV : (MODE == 3) ? addExt : (const float*)nullptr;
    float* C = (MODE == 0) ? g_QKV : (MODE == 1) ? g_QP : (MODE == 2) ? g_RES : Cext;

    __shared__ float As[8][128];
    __shared__ float Bs[8][128];
    int tid  = threadIdx.x;
    int brow = blockIdx.y * 128;
    int bcol = blockIdx.x * 128;
    int ar = tid >> 1, ac = (tid & 1) * 4;
    int br = tid >> 5, bc = (tid & 31) * 4;
    int ty = tid >> 4, tx = tid & 15;

    float acc[8][8];
#pragma unroll
    for (int i = 0; i < 8; i++)
#pragma unroll
        for (int j = 0; j < 8; j++) acc[i][j] = 0.f;

    const float* Aptr = A + (size_t)(brow + ar) * lda + ac;
    const float* Bptr = B + (size_t)br * N + bcol + bc;

    for (int k0 = 0; k0 < Kd; k0 += 8) {
        float4 av = *(const float4*)(Aptr + k0);
        float4 bv = *(const float4*)(Bptr + (size_t)k0 * N);
        __syncthreads();
        As[ac + 0][ar] = av.x; As[ac + 1][ar] = av.y;
        As[ac + 2][ar] = av.z; As[ac + 3][ar] = av.w;
        *(float4*)(&Bs[br][bc]) = bv;
        __syncthreads();
#pragma unroll
        for (int kk = 0; kk < 8; kk++) {
            float a8[8], b8[8];
            *(float4*)(a8)     = *(const float4*)(&As[kk][ty * 8]);
            *(float4*)(a8 + 4) = *(const float4*)(&As[kk][ty * 8 + 4]);
            *(float4*)(b8)     = *(const float4*)(&Bs[kk][tx * 8]);
            *(float4*)(b8 + 4) = *(const float4*)(&Bs[kk][tx * 8 + 4]);
#pragma unroll
            for (int i = 0; i < 8; i++)
#pragma unroll
                for (int j = 0; j < 8; j++)
                    acc[i][j] = fmaf(a8[i], b8[j], acc[i][j]);
        }
    }

    float bb[8];
#pragma unroll
    for (int j = 0; j < 8; j++) bb[j] = bias ? bias[bcol + tx * 8 + j] : 0.f;

#pragma unroll
    for (int i = 0; i < 8; i++) {
        int r = brow + ty * 8 + i;
#pragma unroll
        for (int j = 0; j < 8; j++) {
            int c = bcol + tx * 8 + j;
            float v = acc[i][j] + bb[j];
            if (MODE == 2) v += add[(size_t)r * N + c];
            if (MODE == 3) {
                v += add[(size_t)r * DPD + c];   // + features residual
                C[(size_t)((r >> 12) * DPD + c) * NPTS + (r & 4095)] = v;  // [B,DP,N]
            } else {
                C[(size_t)r * N + c] = v;
            }
        }
    }
}

// ---------------- attention: one warp per point ----------------
__global__ __launch_bounds__(256) void attn_kernel(
    const float* __restrict__ fd1w, const float* __restrict__ fd1b)
{
    int warp = threadIdx.x >> 5, lane = threadIdx.x & 31;
    int p = blockIdx.x * 8 + warp;            // 16384 points
    int d0 = lane * 8;                        // lane owns dims d0..d0+7
    int b = p >> 12;

    const float* qrow = g_QKV + (size_t)p * 768;
    float q[8], qp[8];
    *(float4*)(q)      = *(const float4*)(qrow + d0);
    *(float4*)(q + 4)  = *(const float4*)(qrow + d0 + 4);
    *(float4*)(qp)     = *(const float4*)(g_QP + (size_t)p * 256 + d0);
    *(float4*)(qp + 4) = *(const float4*)(g_QP + (size_t)p * 256 + d0 + 4);

    float f1x[8], f1y[8], f1z[8], hb0[8];
    *(float4*)(f1x)     = *(const float4*)(fd1w + 0 * 256 + d0);
    *(float4*)(f1x + 4) = *(const float4*)(fd1w + 0 * 256 + d0 + 4);
    *(float4*)(f1y)     = *(const float4*)(fd1w + 1 * 256 + d0);
    *(float4*)(f1y + 4) = *(const float4*)(fd1w + 1 * 256 + d0 + 4);
    *(float4*)(f1z)     = *(const float4*)(fd1w + 2 * 256 + d0);
    *(float4*)(f1z + 4) = *(const float4*)(fd1w + 2 * 256 + d0 + 4);
    *(float4*)(hb0)     = *(const float4*)(fd1b + d0);
    *(float4*)(hb0 + 4) = *(const float4*)(fd1b + d0 + 4);

    float4 me = g_pts[p];
    float px = me.x, py = me.y, pz = me.z;
    const int* kidx = g_knn + p * 16;
    const float*  batQKV = g_QKV + (size_t)(b << 12) * 768;
    const float4* batpts = g_pts + (b << 12);

    // ---- pass 1: logits ----
    float mylogit = -1e30f;
    for (int k = 0; k < 16; k++) {
        int idx = __ldg(kidx + k);
        float4 nb = __ldg(batpts + idx);
        float dx = px - nb.x, dy = py - nb.y, dz = pz - nb.z;
        float h[8];
#pragma unroll
        for (int i = 0; i < 8; i++) {
            float t = fmaf(dx, f1x[i], hb0[i]);
            t = fmaf(dy, f1y[i], t);
            t = fmaf(dz, f1z[i], t);
            h[i] = fmaxf(t, 0.f);
        }
        const float* kf = batQKV + (size_t)idx * 768 + 256 + d0;
        float kfv[8];
        *(float4*)(kfv)     = __ldg((const float4*)kf);
        *(float4*)(kfv + 4) = __ldg((const float4*)(kf + 4));
        float s = 0.f;
#pragma unroll
        for (int i = 0; i < 8; i++) {
            s = fmaf(q[i], kfv[i], s);
            s = fmaf(h[i], qp[i], s);    // q . pos  (via qp = fd2 @ q)
        }
#pragma unroll
        for (int o = 16; o >= 1; o >>= 1) s += __shfl_xor_sync(0xffffffffu, s, o);
        if (lane == k) mylogit = s * 0.0625f;   // / sqrt(256)
    }

    // ---- softmax over 16 logits (lane k holds logit k; lanes >=16 hold -inf) ----
    float m = mylogit;
#pragma unroll
    for (int o = 16; o >= 1; o >>= 1) m = fmaxf(m, __shfl_xor_sync(0xffffffffu, m, o));
    float e = expf(mylogit - m);
    float ssum = e;
#pragma unroll
    for (int o = 16; o >= 1; o >>= 1) ssum += __shfl_xor_sync(0xffffffffu, ssum, o);
    float attn = e / ssum;

    // ---- pass 2: weighted sums ----
    float av[8], hbar[8];
#pragma unroll
    for (int i = 0; i < 8; i++) { av[i] = 0.f; hbar[i] = 0.f; }
    for (int k = 0; k < 16; k++) {
        float a = __shfl_sync(0xffffffffu, attn, k);
        int idx = __ldg(kidx + k);
        float4 nb = __ldg(batpts + idx);
        float dx = px - nb.x, dy = py - nb.y, dz = pz - nb.z;
        float h[8];
#pragma unroll
        for (int i = 0; i < 8; i++) {
            float t = fmaf(dx, f1x[i], hb0[i]);
            t = fmaf(dy, f1y[i], t);
            t = fmaf(dz, f1z[i], t);
            h[i] = fmaxf(t, 0.f);
        }
        const float* vf = batQKV + (size_t)idx * 768 + 512 + d0;
        float vv[8];
        *(float4*)(vv)     = __ldg((const float4*)vf);
        *(float4*)(vv + 4) = __ldg((const float4*)(vf + 4));
#pragma unroll
        for (int i = 0; i < 8; i++) {
            av[i]   = fmaf(a, vv[i], av[i]);
            hbar[i] = fmaf(a, h[i], hbar[i]);
        }
    }
    float* avp = g_AV   + (size_t)p * 256 + d0;
    float* hbp = g_HBAR + (size_t)p * 256 + d0;
    *(float4*)(avp)     = *(float4*)(av);
    *(float4*)(avp + 4) = *(float4*)(av + 4);
    *(float4*)(hbp)     = *(float4*)(hbar);
    *(float4*)(hbp + 4) = *(float4*)(hbar + 4);
}

// ---------------- launch ----------------
extern "C" void kernel_launch(void* const* d_in, const int* in_sizes, int n_in,
                              void* d_out, int out_size)
{
    const float* features = (const float*)d_in[0];
    const float* xyz  = (const float*)d_in[1];
    const float* fc1w = (const float*)d_in[2];
    const float* fc1b = (const float*)d_in[3];
    const float* fc2w = (const float*)d_in[4];
    const float* fc2b = (const float*)d_in[5];
    const float* fd1w = (const float*)d_in[6];
    const float* fd1b = (const float*)d_in[7];
    const float* fd2w = (const float*)d_in[8];
    const float* fd2b = (const float*)d_in[9];
    const float* wq   = (const float*)d_in[10];
    const float* wk   = (const float*)d_in[11];
    const float* wv   = (const float*)d_in[12];
    float* out = (float*)d_out;

    prep_wc_k<<<(DPD * 768) / 256, 256>>>(fc1w, fc1b, wq, wk, wv);
    transpose_fd2_k<<<(DMD * DMD) / 256, 256>>>(fd2w);
    pack_xyz_k<<<ROWS / 256, 256>>>(xyz);
    knn_kernel<<<ROWS / 64, 64>>>();

    // QKV = features @ Wc + bc            [16384,768]
    sgemm_k<0><<<dim3(6, 128), 256>>>(features, nullptr, nullptr, nullptr, nullptr,
                                      ROWS, 768, 128, 128);
    // QP = Q @ fd2^T                       [16384,256]
    sgemm_k<1><<<dim3(2, 128), 256>>>(nullptr, nullptr, nullptr, nullptr, nullptr,
                                      ROWS, 256, 256, 768);
    // attention -> AV, HBAR
    attn_kernel<<<ROWS / 8, 256>>>(fd1w, fd1b);
    // RES = HBAR @ fd2 + fd2_b + AV       [16384,256]
    sgemm_k<2><<<dim3(2, 128), 256>>>(nullptr, fd2w, fd2b, nullptr, nullptr,
                                      ROWS, 256, 256, 256);
    // OUT = RES @ fc2 + fc2_b + features  -> transposed [4,128,4096]
    sgemm_k<3><<<dim3(1, 128), 256>>>(nullptr, fc2w, fc2b, features, out,
                                      ROWS, 128, 256, 256);
}

// round 3
// speedup vs baseline: 1.8349x; 1.8349x over previous
#include <cuda_runtime.h>

#define BATCH 4
#define NPTS  4096
#define KNB   16
#define DPD   128
#define DMD   256
#define ROWS  (BATCH * NPTS)   // 16384

// ---------------- scratch (static device globals; no allocations) ----------------
__device__ float  g_Wc[DPD * 768];          // fc1_w @ [wq|wk|wv]  [128,768]
__device__ float  g_bc[768];                // fc1_b @ [wq|wk|wv]
__device__ float  g_fd2T[DMD * DMD];        // fd2^T
__device__ float4 g_pts[ROWS];              // (x,y,z, |xyz|^2)
__device__ int    g_knn[ROWS * KNB];
__device__ float  g_QKV[(size_t)ROWS * 768];// [16384, 768] (q|k|v)
__device__ float  g_QP[ROWS * DMD];         // fd2 @ q per point
__device__ float  g_AV[ROWS * DMD];         // sum_k attn * v
__device__ float  g_HBAR[ROWS * DMD];       // sum_k attn * h
__device__ float  g_RES[ROWS * DMD];

// ---------------- prep: combined qkv weights ----------------
__global__ __launch_bounds__(256) void prep_wc_k(
    const float* __restrict__ fc1w, const float* __restrict__ fc1b,
    const float* __restrict__ wq,   const float* __restrict__ wk,
    const float* __restrict__ wv)
{
    int t = blockIdx.x * 256 + threadIdx.x;   // 0 .. 128*768-1
    int r = t / 768, c = t % 768;
    const float* w = (c < 256) ? wq : (c < 512) ? wk : wv;
    int cc = c & 255;
    float s = 0.f;
#pragma unroll 4
    for (int m = 0; m < 256; m++)
        s = fmaf(__ldg(fc1w + r * 256 + m), __ldg(w + m * 256 + cc), s);
    g_Wc[r * 768 + c] = s;
    if (r == 0) {
        float b = 0.f;
#pragma unroll 4
        for (int m = 0; m < 256; m++)
            b = fmaf(__ldg(fc1b + m), __ldg(w + m * 256 + cc), b);
        g_bc[c] = b;
    }
}

__global__ void transpose_fd2_k(const float* __restrict__ fd2w)
{
    int t = blockIdx.x * 256 + threadIdx.x;   // 65536
    int j = t >> 8, d = t & 255;
    g_fd2T[d * 256 + j] = fd2w[j * 256 + d];
}

__global__ void pack_xyz_k(const float* __restrict__ xyz)
{
    int p = blockIdx.x * 256 + threadIdx.x;   // 16384
    float x = xyz[p * 3], y = xyz[p * 3 + 1], z = xyz[p * 3 + 2];
    float sq = x * x; sq = fmaf(y, y, sq); sq = fmaf(z, z, sq);
    g_pts[p] = make_float4(x, y, z, sq);
}

// ---------------- KNN: warp per query, distributed sorted top-16 ----------------
// Lane i (i < 16) holds element i of the ascending-sorted (dist, idx) list.
// 32 lanes compute 32 candidate distances per iteration; inserts go through a
// ballot-driven serial loop (expected ~105 insert events per query total).
__global__ __launch_bounds__(256) void knn_kernel()
{
    int p    = (blockIdx.x * 256 + threadIdx.x) >> 5;   // query index (warp)
    int lane = threadIdx.x & 31;
    int b = p >> 12;
    const float4* bp = g_pts + (b << 12);
    float4 me = __ldg(bp + (p & 4095));
    float qx = me.x, qy = me.y, qz = me.z, qsq = me.w;

    float ld = 3.0e38f;   // my slot's distance (lanes >=16: overflow garbage)
    int   li = 0;
    float worst = 3.0e38f;

    for (int j0 = 0; j0 < 4096; j0 += 32) {
        float4 o = __ldg(bp + j0 + lane);
        float tt = qx * o.x; tt = fmaf(qy, o.y, tt); tt = fmaf(qz, o.z, tt);
        float d2 = fmaf(-2.f, tt, qsq + o.w);   // exact reference formula
        unsigned ball = __ballot_sync(0xffffffffu, d2 < worst);
        while (ball) {
            int src = __ffs(ball) - 1;
            ball &= ball - 1;
            float v = __shfl_sync(0xffffffffu, d2, src);   // warp-uniform
            if (v < worst) {                                // uniform re-check
                int vi = j0 + src;                          // uniform
                float pd = __shfl_up_sync(0xffffffffu, ld, 1);
                int   pi = __shfl_up_sync(0xffffffffu, li, 1);
                bool pgt = (lane != 0) && (pd > v);
                if (ld > v) {
                    if (pgt) { ld = pd; li = pi; }          // shift right
                    else     { ld = v;  li = vi; }          // insertion point
                }
                worst = __shfl_sync(0xffffffffu, ld, 15);
            }
        }
    }
    if (lane < 16) g_knn[p * 16 + lane] = li;
}

// ---------------- SGEMM: 128x128 block tile, 8x8 microtile, BK=8 ----------------
// MODE 0: QKV = features @ g_Wc + g_bc
// MODE 1: QP  = Q(g_QKV cols 0:256, lda=768) @ g_fd2T
// MODE 2: RES = g_HBAR @ fd2_w + fd2_b + g_AV
// MODE 3: OUT = g_RES @ fc2_w + fc2_b + features   (stored transposed [B,DP,N])
template<int MODE>
__global__ __launch_bounds__(256) void sgemm_k(
    const float* __restrict__ Aext, const float* __restrict__ Bext,
    const float* __restrict__ biasExt, const float* __restrict__ addExt,
    float* __restrict__ Cext, int M, int N, int Kd, int lda)
{
    const float* A = (MODE == 0) ? Aext : (MODE == 1) ? g_QKV : (MODE == 2) ? g_HBAR : g_RES;
    const float* B = (MODE == 0) ? g_Wc : (MODE == 1) ? g_fd2T : Bext;
    const float* bias = (MODE == 0) ? g_bc : (MODE == 1) ? (const float*)nullptr : biasExt;
    const float* add  = (MODE == 2) ? g_AV : (MODE == 3) ? addExt : (const float*)nullptr;
    float* C = (MODE == 0) ? g_QKV : (MODE == 1) ? g_QP : (MODE == 2) ? g_RES : Cext;

    __shared__ float As[8][128];
    __shared__ float Bs[8][128];
    int tid  = threadIdx.x;
    int brow = blockIdx.y * 128;
    int bcol = blockIdx.x * 128;
    int ar = tid >> 1, ac = (tid & 1) * 4;
    int br = tid >> 5, bc = (tid & 31) * 4;
    int ty = tid >> 4, tx = tid & 15;

    float acc[8][8];
#pragma unroll
    for (int i = 0; i < 8; i++)
#pragma unroll
        for (int j = 0; j < 8; j++) acc[i][j] = 0.f;

    const float* Aptr = A + (size_t)(brow + ar) * lda + ac;
    const float* Bptr = B + (size_t)br * N + bcol + bc;

    for (int k0 = 0; k0 < Kd; k0 += 8) {
        float4 av = *(const float4*)(Aptr + k0);
        float4 bv = *(const float4*)(Bptr + (size_t)k0 * N);
        __syncthreads();
        As[ac + 0][ar] = av.x; As[ac + 1][ar] = av.y;
        As[ac + 2][ar] = av.z; As[ac + 3][ar] = av.w;
        *(float4*)(&Bs[br][bc]) = bv;
        __syncthreads();
#pragma unroll
        for (int kk = 0; kk < 8; kk++) {
            float a8[8], b8[8];
            *(float4*)(a8)     = *(const float4*)(&As[kk][ty * 8]);
            *(float4*)(a8 + 4) = *(const float4*)(&As[kk][ty * 8 + 4]);
            *(float4*)(b8)     = *(const float4*)(&Bs[kk][tx * 8]);
            *(float4*)(b8 + 4) = *(const float4*)(&Bs[kk][tx * 8 + 4]);
#pragma unroll
            for (int i = 0; i < 8; i++)
#pragma unroll
                for (int j = 0; j < 8; j++)
                    acc[i][j] = fmaf(a8[i], b8[j], acc[i][j]);
        }
    }

    float bb[8];
#pragma unroll
    for (int j = 0; j < 8; j++) bb[j] = bias ? bias[bcol + tx * 8 + j] : 0.f;

#pragma unroll
    for (int i = 0; i < 8; i++) {
        int r = brow + ty * 8 + i;
#pragma unroll
        for (int j = 0; j < 8; j++) {
            int c = bcol + tx * 8 + j;
            float v = acc[i][j] + bb[j];
            if (MODE == 2) v += add[(size_t)r * N + c];
            if (MODE == 3) {
                v += add[(size_t)r * DPD + c];   // + features residual
                C[(size_t)((r >> 12) * DPD + c) * NPTS + (r & 4095)] = v;  // [B,DP,N]
            } else {
                C[(size_t)r * N + c] = v;
            }
        }
    }
}

// ---------------- attention: one warp per point ----------------
__global__ __launch_bounds__(256) void attn_kernel(
    const float* __restrict__ fd1w, const float* __restrict__ fd1b)
{
    int warp = threadIdx.x >> 5, lane = threadIdx.x & 31;
    int p = blockIdx.x * 8 + warp;            // 16384 points
    int d0 = lane * 8;                        // lane owns dims d0..d0+7
    int b = p >> 12;

    const float* qrow = g_QKV + (size_t)p * 768;
    float q[8], qp[8];
    *(float4*)(q)      = *(const float4*)(qrow + d0);
    *(float4*)(q + 4)  = *(const float4*)(qrow + d0 + 4);
    *(float4*)(qp)     = *(const float4*)(g_QP + (size_t)p * 256 + d0);
    *(float4*)(qp + 4) = *(const float4*)(g_QP + (size_t)p * 256 + d0 + 4);

    float f1x[8], f1y[8], f1z[8], hb0[8];
    *(float4*)(f1x)     = *(const float4*)(fd1w + 0 * 256 + d0);
    *(float4*)(f1x + 4) = *(const float4*)(fd1w + 0 * 256 + d0 + 4);
    *(float4*)(f1y)     = *(const float4*)(fd1w + 1 * 256 + d0);
    *(float4*)(f1y + 4) = *(const float4*)(fd1w + 1 * 256 + d0 + 4);
    *(float4*)(f1z)     = *(const float4*)(fd1w + 2 * 256 + d0);
    *(float4*)(f1z + 4) = *(const float4*)(fd1w + 2 * 256 + d0 + 4);
    *(float4*)(hb0)     = *(const float4*)(fd1b + d0);
    *(float4*)(hb0 + 4) = *(const float4*)(fd1b + d0 + 4);

    float4 me = g_pts[p];
    float px = me.x, py = me.y, pz = me.z;
    const int* kidx = g_knn + p * 16;
    const float*  batQKV = g_QKV + (size_t)(b << 12) * 768;
    const float4* batpts = g_pts + (b << 12);

    // ---- pass 1: logits ----
    float mylogit = -1e30f;
    for (int k = 0; k < 16; k++) {
        int idx = __ldg(kidx + k);
        float4 nb = __ldg(batpts + idx);
        float dx = px - nb.x, dy = py - nb.y, dz = pz - nb.z;
        float h[8];
#pragma unroll
        for (int i = 0; i < 8; i++) {
            float t = fmaf(dx, f1x[i], hb0[i]);
            t = fmaf(dy, f1y[i], t);
            t = fmaf(dz, f1z[i], t);
            h[i] = fmaxf(t, 0.f);
        }
        const float* kf = batQKV + (size_t)idx * 768 + 256 + d0;
        float kfv[8];
        *(float4*)(kfv)     = __ldg((const float4*)kf);
        *(float4*)(kfv + 4) = __ldg((const float4*)(kf + 4));
        float s = 0.f;
#pragma unroll
        for (int i = 0; i < 8; i++) {
            s = fmaf(q[i], kfv[i], s);
            s = fmaf(h[i], qp[i], s);    // q . pos  (via qp = fd2 @ q)
        }
#pragma unroll
        for (int o = 16; o >= 1; o >>= 1) s += __shfl_xor_sync(0xffffffffu, s, o);
        if (lane == k) mylogit = s * 0.0625f;   // / sqrt(256)
    }

    // ---- softmax over 16 logits (lane k holds logit k; lanes >=16 hold -inf) ----
    float m = mylogit;
#pragma unroll
    for (int o = 16; o >= 1; o >>= 1) m = fmaxf(m, __shfl_xor_sync(0xffffffffu, m, o));
    float e = expf(mylogit - m);
    float ssum = e;
#pragma unroll
    for (int o = 16; o >= 1; o >>= 1) ssum += __shfl_xor_sync(0xffffffffu, ssum, o);
    float attn = e / ssum;

    // ---- pass 2: weighted sums ----
    float av[8], hbar[8];
#pragma unroll
    for (int i = 0; i < 8; i++) { av[i] = 0.f; hbar[i] = 0.f; }
    for (int k = 0; k < 16; k++) {
        float a = __shfl_sync(0xffffffffu, attn, k);
        int idx = __ldg(kidx + k);
        float4 nb = __ldg(batpts + idx);
        float dx = px - nb.x, dy = py - nb.y, dz = pz - nb.z;
        float h[8];
#pragma unroll
        for (int i = 0; i < 8; i++) {
            float t = fmaf(dx, f1x[i], hb0[i]);
            t = fmaf(dy, f1y[i], t);
            t = fmaf(dz, f1z[i], t);
            h[i] = fmaxf(t, 0.f);
        }
        const float* vf = batQKV + (size_t)idx * 768 + 512 + d0;
        float vv[8];
        *(float4*)(vv)     = __ldg((const float4*)vf);
        *(float4*)(vv + 4) = __ldg((const float4*)(vf + 4));
#pragma unroll
        for (int i = 0; i < 8; i++) {
            av[i]   = fmaf(a, vv[i], av[i]);
            hbar[i] = fmaf(a, h[i], hbar[i]);
        }
    }
    float* avp = g_AV   + (size_t)p * 256 + d0;
    float* hbp = g_HBAR + (size_t)p * 256 + d0;
    *(float4*)(avp)     = *(float4*)(av);
    *(float4*)(avp + 4) = *(float4*)(av + 4);
    *(float4*)(hbp)     = *(float4*)(hbar);
    *(float4*)(hbp + 4) = *(float4*)(hbar + 4);
}

// ---------------- launch ----------------
extern "C" void kernel_launch(void* const* d_in, const int* in_sizes, int n_in,
                              void* d_out, int out_size)
{
    const float* features = (const float*)d_in[0];
    const float* xyz  = (const float*)d_in[1];
    const float* fc1w = (const float*)d_in[2];
    const float* fc1b = (const float*)d_in[3];
    const float* fc2w = (const float*)d_in[4];
    const float* fc2b = (const float*)d_in[5];
    const float* fd1w = (const float*)d_in[6];
    const float* fd1b = (const float*)d_in[7];
    const float* fd2w = (const float*)d_in[8];
    const float* fd2b = (const float*)d_in[9];
    const float* wq   = (const float*)d_in[10];
    const float* wk   = (const float*)d_in[11];
    const float* wv   = (const float*)d_in[12];
    float* out = (float*)d_out;

    prep_wc_k<<<(DPD * 768) / 256, 256>>>(fc1w, fc1b, wq, wk, wv);
    transpose_fd2_k<<<(DMD * DMD) / 256, 256>>>(fd2w);
    pack_xyz_k<<<ROWS / 256, 256>>>(xyz);
    knn_kernel<<<ROWS / 8, 256>>>();   // warp per query: 16384 warps

    // QKV = features @ Wc + bc            [16384,768]
    sgemm_k<0><<<dim3(6, 128), 256>>>(features, nullptr, nullptr, nullptr, nullptr,
                                      ROWS, 768, 128, 128);
    // QP = Q @ fd2^T                       [16384,256]
    sgemm_k<1><<<dim3(2, 128), 256>>>(nullptr, nullptr, nullptr, nullptr, nullptr,
                                      ROWS, 256, 256, 768);
    // attention -> AV, HBAR
    attn_kernel<<<ROWS / 8, 256>>>(fd1w, fd1b);
    // RES = HBAR @ fd2 + fd2_b + AV       [16384,256]
    sgemm_k<2><<<dim3(2, 128), 256>>>(nullptr, fd2w, fd2b, nullptr, nullptr,
                                      ROWS, 256, 256, 256);
    // OUT = RES @ fc2 + fc2_b + features  -> transposed [4,128,4096]
    sgemm_k<3><<<dim3(1, 128), 256>>>(nullptr, fc2w, fc2b, features, out,
                                      ROWS, 128, 256, 256);
}